// round 6
// baseline (speedup 1.0000x reference)
#include <cuda_runtime.h>

// InteractionArch: out[b] = concat(dense[b] (128), sparse[b]·dense[b] (26),
//                                  triu_{k=1}(sparse[b]·sparse[b]^T) (325))
// B=16384, F=26, D=128, out stride 479 fp32 (row base only 4B-aligned).
//
// R6: R5 pipeline (k-chunked, double-buffered cp.async, 7x7 reg tiles,
// 3 rows/warp, 10 single-warp blocks/SM) + packed fma.rn.f32x2 compute:
// each float4 smem load = two aligned b64 pairs, 2 FFMA2 per tile pair per
// quad-step instead of 4 FFMA. Halves the FMA issue-slot load.

#define B_TOT 16384
#define NF 26
#define DD 128
#define NV 28
#define CHUNK 32          // floats per k-chunk
#define CQ 8              // quads per chunk
#define NCH 4             // chunks (128/32)
#define OUT_STRIDE 479
#define RPW 3             // batch rows per warp

__device__ __forceinline__ void cp_async16(void* smem, const void* gmem) {
    unsigned s = (unsigned)__cvta_generic_to_shared(smem);
    asm volatile("cp.async.cg.shared.global [%0], [%1], 16;" :: "r"(s), "l"(gmem));
}
__device__ __forceinline__ void cp_commit() {
    asm volatile("cp.async.commit_group;");
}
template <int N>
__device__ __forceinline__ void cp_wait() {
    asm volatile("cp.async.wait_group %0;" :: "n"(N));
}
// packed f32x2 fma: acc(2xf32) += a(2xf32) * b(2xf32)
__device__ __forceinline__ void ffma2(unsigned long long& acc,
                                      unsigned long long a,
                                      unsigned long long b) {
    asm("fma.rn.f32x2 %0, %1, %2, %0;" : "+l"(acc) : "l"(a), "l"(b));
}

__global__ void __launch_bounds__(32, 10) interact_kernel(
    const float* __restrict__ dense,
    const float* __restrict__ sparse,
    float* __restrict__ out)
{
    __shared__ float Xs[RPW][2][NV][CHUNK];   // 21504 B

    const int lane = threadIdx.x;
    const int b0   = blockIdx.x * RPW;

    // ---- zero pad slot 27 (both buffers, never overwritten) ----
    #pragma unroll
    for (int t = 0; t < 6; t++) {
        int idx = lane + 32 * t;           // RPW*2*CHUNK = 192 floats
        int rr  = idx / (2 * CHUNK);
        int rem = idx - rr * 2 * CHUNK;
        Xs[rr][rem / CHUNK][27][rem % CHUNK] = 0.f;
    }

    // ---- dense passthrough to out[0:128] (scalar stores) ----
    #pragma unroll
    for (int r = 0; r < RPW; r++) {
        const int b = b0 + r;
        if (b >= B_TOT) break;
        float4 dv = reinterpret_cast<const float4*>(dense + (size_t)b * DD)[lane];
        float* ob = out + (size_t)b * OUT_STRIDE;
        ob[4 * lane + 0] = dv.x;
        ob[4 * lane + 1] = dv.y;
        ob[4 * lane + 2] = dv.z;
        ob[4 * lane + 3] = dv.w;
    }

    // ---- chunk loader (warp-cooperative) ----
    auto load_chunk = [&](int c, int buf) {
        #pragma unroll
        for (int t = 0; t < 20; t++) {
            int idx = lane + 32 * t;
            if (idx < NF * CQ * RPW) {
                int r   = idx / (NF * CQ);
                int rem = idx - r * NF * CQ;
                int v   = rem >> 3;
                int q   = rem & 7;
                int b   = b0 + r;
                if (b < B_TOT) {
                    const float* g = sparse + (size_t)b * NF * DD + v * DD + c * CHUNK + q * 4;
                    cp_async16(&Xs[r][buf][v][q * 4], g);
                }
            }
        }
        if (lane < CQ * RPW) {
            int r = lane >> 3, q = lane & 7;
            int b = b0 + r;
            if (b < B_TOT)
                cp_async16(&Xs[r][buf][26][q * 4],
                           dense + (size_t)b * DD + c * CHUNK + q * 4);
        }
        cp_commit();
    };

    // ---- lane -> (row, tile) mapping for compute ----
    const int r  = lane / 10;                 // 0..2 (lanes 30,31 idle in compute)
    const int t  = lane - r * 10;             // 0..9
    const int bc = b0 + r;
    const bool active = (lane < 30) && (bc < B_TOT);

    const int ti = (t < 4) ? 0 : (t < 7) ? 1 : (t < 9) ? 2 : 3;
    const int tj = (t < 4) ? t : (t < 7) ? t - 3 : (t < 9) ? t - 5 : 3;

    unsigned long long acc2[7][7];            // packed f32x2 partial sums
    #pragma unroll
    for (int ii = 0; ii < 7; ii++)
        #pragma unroll
        for (int jj = 0; jj < 7; jj++)
            acc2[ii][jj] = 0ULL;

    // ---- pipelined chunk loop ----
    load_chunk(0, 0);
    #pragma unroll
    for (int c = 0; c < NCH; c++) {
        const int buf = c & 1;
        if (c + 1 < NCH) { load_chunk(c + 1, buf ^ 1); cp_wait<1>(); }
        else             { cp_wait<0>(); }
        __syncwarp();

        if (active) {
            // each row of the chunk viewed as 8 x (2 x f32x2) = ulonglong2[8]
            const ulonglong2* __restrict__ pi2 =
                reinterpret_cast<const ulonglong2*>(&Xs[r][buf][7 * ti][0]);
            const ulonglong2* __restrict__ pj2 =
                reinterpret_cast<const ulonglong2*>(&Xs[r][buf][7 * tj][0]);
            #pragma unroll 1
            for (int kk = 0; kk < CQ; kk++) {
                const int kq = (kk + lane) & (CQ - 1);
                ulonglong2 xi[7], xj[7];
                #pragma unroll
                for (int ii = 0; ii < 7; ii++) xi[ii] = pi2[ii * CQ + kq];
                #pragma unroll
                for (int jj = 0; jj < 7; jj++) xj[jj] = pj2[jj * CQ + kq];
                #pragma unroll
                for (int ii = 0; ii < 7; ii++)
                    #pragma unroll
                    for (int jj = 0; jj < 7; jj++) {
                        ffma2(acc2[ii][jj], xi[ii].x, xj[jj].x);
                        ffma2(acc2[ii][jj], xi[ii].y, xj[jj].y);
                    }
            }
        }
        __syncwarp();   // all lanes done reading buf before it is refilled
    }

    // ---- epilogue: horizontal add + scatter needed dots (i<j, j<=26) ----
    if (!active) return;
    float* ob = out + (size_t)bc * OUT_STRIDE;
    #pragma unroll
    for (int ii = 0; ii < 7; ii++) {
        #pragma unroll
        for (int jj = 0; jj < 7; jj++) {
            const int i = 7 * ti + ii;
            const int j = 7 * tj + jj;
            if (i < j && j <= 26) {
                float2 p = *reinterpret_cast<float2*>(&acc2[ii][jj]);
                float v = p.x + p.y;
                int dst;
                if (j == 26) {
                    dst = 128 + i;                                        // sparse·dense
                } else {
                    dst = 154 + i * 25 - (i * (i - 1)) / 2 + (j - i - 1); // pair
                }
                ob[dst] = v;
            }
        }
    }
}

extern "C" void kernel_launch(void* const* d_in, const int* in_sizes, int n_in,
                              void* d_out, int out_size)
{
    (void)n_in; (void)out_size;
    const float* a = (const float*)d_in[0];
    const float* b = (const float*)d_in[1];
    // dense has B*D = 2,097,152 elems; sparse has B*F*D = 54,525,952 elems.
    const float* dense  = (in_sizes[0] < in_sizes[1]) ? a : b;
    const float* sparse = (in_sizes[0] < in_sizes[1]) ? b : a;

    const int grid = (B_TOT + RPW - 1) / RPW;
    interact_kernel<<<grid, 32>>>(dense, sparse, (float*)d_out);
}

// round 7
// speedup vs baseline: 1.1082x; 1.1082x over previous
#include <cuda_runtime.h>

// InteractionArch: out[b] = concat(dense[b] (128), sparse[b]·dense[b] (26),
//                                  triu_{k=1}(sparse[b]·sparse[b]^T) (325))
// B=16384, F=26, D=128, out stride 479 fp32 (row base only 4B-aligned).
//
// R7: occupancy-first. 4x4 register tiles over the 28-vector set (7x7 tile
// grid, 28 upper-tri tiles incl diagonal), 1 lane/tile, 1 batch row/warp.
// Double-buffered cp.async k-chunks (32 floats) + packed fma.rn.f32x2.
// ~90 regs, 7.2KB smem -> __launch_bounds__(32,20): 20 warps/SM (2x R6).

#define B_TOT 16384
#define NF 26
#define DD 128
#define NV 28
#define CHUNK 32          // floats per k-chunk
#define CQ 8              // float4 quads per chunk
#define NCH 4             // chunks (128/32)
#define OUT_STRIDE 479

__device__ __forceinline__ void cp_async16(void* smem, const void* gmem) {
    unsigned s = (unsigned)__cvta_generic_to_shared(smem);
    asm volatile("cp.async.cg.shared.global [%0], [%1], 16;" :: "r"(s), "l"(gmem));
}
__device__ __forceinline__ void cp_commit() {
    asm volatile("cp.async.commit_group;");
}
template <int N>
__device__ __forceinline__ void cp_wait() {
    asm volatile("cp.async.wait_group %0;" :: "n"(N));
}
// packed f32x2 fma: acc(2xf32) += a(2xf32) * b(2xf32)
__device__ __forceinline__ void ffma2(unsigned long long& acc,
                                      unsigned long long a,
                                      unsigned long long b) {
    asm("fma.rn.f32x2 %0, %1, %2, %0;" : "+l"(acc) : "l"(a), "l"(b));
}

__global__ void __launch_bounds__(32, 20) interact_kernel(
    const float* __restrict__ dense,
    const float* __restrict__ sparse,
    float* __restrict__ out)
{
    __shared__ float Xs[2][NV][CHUNK];   // 7168 B

    const int lane = threadIdx.x;
    const int b    = blockIdx.x;

    // ---- zero pad slot 27 (both buffers, never overwritten) ----
    if (lane < 2 * CHUNK / 2) {          // 32 lanes: 2 floats each
        Xs[0][27][lane] = 0.f;
        Xs[1][27][lane] = 0.f;
        Xs[0][27][lane + 0] = 0.f;       // (idempotent; keep simple)
    }
    Xs[0][27][lane] = 0.f;
    Xs[1][27][lane] = 0.f;

    // ---- dense passthrough to out[0:128] (scalar stores; base only 4B-aligned) ----
    {
        float4 dv = reinterpret_cast<const float4*>(dense + (size_t)b * DD)[lane];
        float* ob = out + (size_t)b * OUT_STRIDE;
        ob[4 * lane + 0] = dv.x;
        ob[4 * lane + 1] = dv.y;
        ob[4 * lane + 2] = dv.z;
        ob[4 * lane + 3] = dv.w;
    }

    const float* __restrict__ spb = sparse + (size_t)b * NF * DD;
    const float* __restrict__ dnb = dense + (size_t)b * DD;

    // ---- chunk loader (warp-cooperative): 26*8 sparse + 8 dense quads ----
    auto load_chunk = [&](int c, int buf) {
        #pragma unroll
        for (int t = 0; t < 7; t++) {
            int idx = lane + 32 * t;
            if (idx < NF * CQ) {
                int v = idx >> 3;
                int q = idx & 7;
                cp_async16(&Xs[buf][v][q * 4], spb + v * DD + c * CHUNK + q * 4);
            }
        }
        if (lane < CQ) {
            cp_async16(&Xs[buf][26][lane * 4], dnb + c * CHUNK + lane * 4);
        }
        cp_commit();
    };

    // ---- lane -> 4x4 tile mapping: 28 upper-tri tiles of the 7x7 grid ----
    int ti = 0, rem = lane;
    #pragma unroll
    for (int s = 0; s < 6; s++) {
        if (rem >= 7 - ti) { rem -= 7 - ti; ti++; }
    }
    const int tj = ti + rem;
    const int i0 = 4 * ti;
    const int j0 = 4 * tj;
    const bool active = (lane < 28);

    unsigned long long acc2[4][4];       // packed f32x2 partial sums
    #pragma unroll
    for (int ii = 0; ii < 4; ii++)
        #pragma unroll
        for (int jj = 0; jj < 4; jj++)
            acc2[ii][jj] = 0ULL;

    // ---- pipelined chunk loop ----
    load_chunk(0, 0);
    #pragma unroll
    for (int c = 0; c < NCH; c++) {
        const int buf = c & 1;
        if (c + 1 < NCH) { load_chunk(c + 1, buf ^ 1); cp_wait<1>(); }
        else             { cp_wait<0>(); }
        __syncwarp();

        if (active) {
            const ulonglong2* __restrict__ pi2 =
                reinterpret_cast<const ulonglong2*>(&Xs[buf][i0][0]);
            const ulonglong2* __restrict__ pj2 =
                reinterpret_cast<const ulonglong2*>(&Xs[buf][j0][0]);
            #pragma unroll 2
            for (int kk = 0; kk < CQ; kk++) {
                const int kq = (kk + lane) & (CQ - 1);
                ulonglong2 xi[4], xj[4];
                #pragma unroll
                for (int ii = 0; ii < 4; ii++) xi[ii] = pi2[ii * CQ + kq];
                #pragma unroll
                for (int jj = 0; jj < 4; jj++) xj[jj] = pj2[jj * CQ + kq];
                #pragma unroll
                for (int ii = 0; ii < 4; ii++)
                    #pragma unroll
                    for (int jj = 0; jj < 4; jj++) {
                        ffma2(acc2[ii][jj], xi[ii].x, xj[jj].x);
                        ffma2(acc2[ii][jj], xi[ii].y, xj[jj].y);
                    }
            }
        }
        __syncwarp();   // all lanes done reading buf before it is refilled
    }

    // ---- epilogue: horizontal add + scatter needed dots (i<j, j<=26) ----
    if (!active) return;
    float* ob = out + (size_t)b * OUT_STRIDE;
    #pragma unroll
    for (int ii = 0; ii < 4; ii++) {
        #pragma unroll
        for (int jj = 0; jj < 4; jj++) {
            const int i = i0 + ii;
            const int j = j0 + jj;
            if (i < j && j <= 26) {
                float2 p = *reinterpret_cast<float2*>(&acc2[ii][jj]);
                float v = p.x + p.y;
                int dst;
                if (j == 26) {
                    dst = 128 + i;                                        // sparse·dense
                } else {
                    dst = 154 + i * 25 - (i * (i - 1)) / 2 + (j - i - 1); // pair
                }
                ob[dst] = v;
            }
        }
    }
}

extern "C" void kernel_launch(void* const* d_in, const int* in_sizes, int n_in,
                              void* d_out, int out_size)
{
    (void)n_in; (void)out_size;
    const float* a = (const float*)d_in[0];
    const float* b = (const float*)d_in[1];
    // dense has B*D = 2,097,152 elems; sparse has B*F*D = 54,525,952 elems.
    const float* dense  = (in_sizes[0] < in_sizes[1]) ? a : b;
    const float* sparse = (in_sizes[0] < in_sizes[1]) ? b : a;

    interact_kernel<<<B_TOT, 32>>>(dense, sparse, (float*)d_out);
}